// round 12
// baseline (speedup 1.0000x reference)
#include <cuda_runtime.h>
#include <cstdint>

// ============================================================================
// TF32 mma.sync GEMM: out[32768,512] = X @ W^T + bias.
// R8 skeleton + X ALSO pre-rounded (cvt.rna.tf32) and column-permuted into a
// 64MB __device__ scratch by a streaming prepass. GEMM inner loop is
// 24 LDS.128 + 64 MMA per warp-chunk, ZERO cvt, all-vector fragment loads.
// Perm (within each 16-col group): src col 4s+t -> dst col 4t+s.
// BM=BN=128, BK=32, 2-stage cp.async, 8 warps (4x2), warp tile 32x64, m16n8k8.
// SS=48 floats/row: LDS.128 fragment loads are bank-conflict-free.
// (Resubmit of R11 — infra container failure, kernel never ran. Prepasses
//  merged into one grid-stride launch; math bit-identical.)
// ============================================================================

#define MTOT 32768
#define KTOT 512
#define NTOT 512
#define BM   128
#define BN   128
#define BK   32
#define NKC  (KTOT / BK)     // 16
#define THREADS 256
#define SS   48              // smem floats per row (32 data + 16 pad)

#define TILE_FLOATS (128 * SS)   // 6144 floats per operand stage

__device__ float Xperm[(size_t)MTOT * KTOT];   // 64MB scratch
__device__ float Wperm[(size_t)NTOT * KTOT];   // 1MB scratch

__device__ __forceinline__ uint32_t smem_u32(const void* p) {
    return (uint32_t)__cvta_generic_to_shared(p);
}

__device__ __forceinline__ float tf32rnf(float x) {
    uint32_t y;
    asm("cvt.rna.tf32.f32 %0, %1;" : "=r"(y) : "f"(x));
    return __uint_as_float(y);
}

#define CP_ASYNC_CG(dst_u32, src_ptr)                                         \
    asm volatile("cp.async.cg.shared.global [%0], [%1], 16;"                  \
                 :: "r"(dst_u32), "l"(src_ptr))
#define CP_COMMIT() asm volatile("cp.async.commit_group;" ::: "memory")
#define CP_WAIT(N)  asm volatile("cp.async.wait_group %0;" :: "n"(N) : "memory")

__device__ __forceinline__ void mma_tf32(float* d, const uint32_t* a,
                                         const uint32_t* b) {
    asm volatile(
        "mma.sync.aligned.m16n8k8.row.col.f32.tf32.tf32.f32 "
        "{%0,%1,%2,%3}, {%4,%5,%6,%7}, {%8,%9}, {%0,%1,%2,%3};"
        : "+f"(d[0]), "+f"(d[1]), "+f"(d[2]), "+f"(d[3])
        : "r"(a[0]), "r"(a[1]), "r"(a[2]), "r"(a[3]), "r"(b[0]), "r"(b[1]));
}

// Prepass (grid-stride over X then W):
// dst[row][g16*16 + 4t+s] = tf32_round(src[row][g16*16 + 4s+t]).
// Each thread produces one output float4 (gathers 4 stride-4 scalars).
__global__ void __launch_bounds__(256)
prep_kernel(const float* __restrict__ X, const float* __restrict__ W) {
    const int NX = MTOT * (KTOT / 4);          // float4 outputs for X
    const int NTOTAL = NX + NTOT * (KTOT / 4); // + for W
    for (int idx = blockIdx.x * 256 + threadIdx.x; idx < NTOTAL;
         idx += gridDim.x * 256) {
        const float* src;
        float* dst;
        int li;
        if (idx < NX) { src = X;  dst = Xperm; li = idx; }
        else          { src = W;  dst = Wperm; li = idx - NX; }
        const int row = li >> 7;           // 128 float4 per row
        const int q   = li & 127;
        const int g16 = q >> 2;            // 16-col group
        const int tp  = q & 3;             // output float4 index within group
        const float* s = src + (size_t)row * KTOT + g16 * 16 + tp;
        float4 o;
        o.x = tf32rnf(s[0]);
        o.y = tf32rnf(s[4]);
        o.z = tf32rnf(s[8]);
        o.w = tf32rnf(s[12]);
        *reinterpret_cast<float4*>(dst + (size_t)row * KTOT + g16 * 16 + tp * 4) = o;
    }
}

__global__ void __launch_bounds__(THREADS, 2)
linear_tf32_kernel(const float* __restrict__ bias, float* __restrict__ out) {
    extern __shared__ float smem[];
    float* As = smem;                           // [2][TILE_FLOATS]
    float* Bs = smem + 2 * TILE_FLOATS;         // [2][TILE_FLOATS]
    float* bias_s = smem + 4 * TILE_FLOATS;     // [BN]

    const int tid = threadIdx.x;
    const int wid = tid >> 5;
    const int lid = tid & 31;
    const int g = lid >> 2;          // group id (0..7)
    const int t = lid & 3;           // thread-in-group (0..3)
    const int wm = (wid & 3) * 32;   // warp M offset
    const int wn = (wid >> 2) * 64;  // warp N offset

    const int n0 = blockIdx.x * BN;
    const int m0 = blockIdx.y * BM;

    const float* Ag = Xperm + (size_t)m0 * KTOT;
    const float* Bg = Wperm + (size_t)n0 * KTOT;

    if (tid < BN) bias_s[tid] = bias[n0 + tid];

    const uint32_t as_b = smem_u32(As);
    const uint32_t bs_b = smem_u32(Bs);

    // Staging: idx in [0,1024): row = idx>>3, ch = idx&7 (16B chunks).
    const int sr0 = tid >> 3;
    const int sch = (tid & 7) * 4;

    // -------- prologue: stage chunk 0 --------
    {
        #pragma unroll
        for (int i = 0; i < 4; i++) {
            const int row = sr0 + i * 32;
            CP_ASYNC_CG(as_b + (row * SS + sch) * 4, Ag + (size_t)row * KTOT + sch);
        }
        #pragma unroll
        for (int i = 0; i < 4; i++) {
            const int row = sr0 + i * 32;
            CP_ASYNC_CG(bs_b + (row * SS + sch) * 4, Bg + (size_t)row * KTOT + sch);
        }
        CP_COMMIT();
    }

    float acc[2][8][4];
    #pragma unroll
    for (int mi = 0; mi < 2; mi++)
        #pragma unroll
        for (int nj = 0; nj < 8; nj++)
            #pragma unroll
            for (int e = 0; e < 4; e++) acc[mi][nj][e] = 0.0f;

    for (int kc = 0; kc < NKC; kc++) {
        const int s = kc & 1;

        CP_WAIT(0);         // chunk kc landed
        __syncthreads();    // stage s^1 drained by all warps

        // Prefetch chunk kc+1 into stage s^1 (safe: after barrier).
        if (kc + 1 < NKC) {
            const int kb = (kc + 1) * BK;
            const uint32_t an = as_b + (s ^ 1) * TILE_FLOATS * 4;
            const uint32_t bn = bs_b + (s ^ 1) * TILE_FLOATS * 4;
            #pragma unroll
            for (int i = 0; i < 4; i++) {
                const int row = sr0 + i * 32;
                CP_ASYNC_CG(an + (row * SS + sch) * 4,
                            Ag + (size_t)row * KTOT + kb + sch);
            }
            #pragma unroll
            for (int i = 0; i < 4; i++) {
                const int row = sr0 + i * 32;
                CP_ASYNC_CG(bn + (row * SS + sch) * 4,
                            Bg + (size_t)row * KTOT + kb + sch);
            }
            CP_COMMIT();
        }

        const float* At = As + s * TILE_FLOATS;
        const float* Bt = Bs + s * TILE_FLOATS;

        #pragma unroll
        for (int G = 0; G < 2; G++) {   // two 16-K groups per chunk
            const int go = G * 16 + 4 * t;

            // A fragments: 4 x LDS.128, zero cvt.
            uint32_t af0[2][4], af1[2][4];
            #pragma unroll
            for (int mi = 0; mi < 2; mi++) {
                const int r = wm + mi * 16 + g;
                const float4 v  = *reinterpret_cast<const float4*>(At + r * SS + go);
                const float4 v8 = *reinterpret_cast<const float4*>(At + (r + 8) * SS + go);
                af0[mi][0] = __float_as_uint(v.x);  af0[mi][1] = __float_as_uint(v8.x);
                af0[mi][2] = __float_as_uint(v.y);  af0[mi][3] = __float_as_uint(v8.y);
                af1[mi][0] = __float_as_uint(v.z);  af1[mi][1] = __float_as_uint(v8.z);
                af1[mi][2] = __float_as_uint(v.w);  af1[mi][3] = __float_as_uint(v8.w);
            }

            // B fragments: 8 x LDS.128, zero cvt.
            uint32_t bf0[8][2], bf1[8][2];
            #pragma unroll
            for (int nj = 0; nj < 8; nj++) {
                const int n = wn + nj * 8 + g;
                const float4 v = *reinterpret_cast<const float4*>(Bt + n * SS + go);
                bf0[nj][0] = __float_as_uint(v.x);
                bf0[nj][1] = __float_as_uint(v.y);
                bf1[nj][0] = __float_as_uint(v.z);
                bf1[nj][1] = __float_as_uint(v.w);
            }

            #pragma unroll
            for (int mi = 0; mi < 2; mi++)
                #pragma unroll
                for (int nj = 0; nj < 8; nj++)
                    mma_tf32(acc[mi][nj], af0[mi], bf0[nj]);
            #pragma unroll
            for (int mi = 0; mi < 2; mi++)
                #pragma unroll
                for (int nj = 0; nj < 8; nj++)
                    mma_tf32(acc[mi][nj], af1[mi], bf1[nj]);
        }
    }

    // -------- epilogue: add bias, store float2 --------
    // (K-permutation only reorders the contraction; output layout untouched.)
    #pragma unroll
    for (int mi = 0; mi < 2; mi++) {
        const int r0 = m0 + wm + mi * 16 + g;
        #pragma unroll
        for (int nj = 0; nj < 8; nj++) {
            const int cl = wn + nj * 8 + 2 * t;
            const float bx = bias_s[cl];
            const float by = bias_s[cl + 1];
            float2 v0 = make_float2(acc[mi][nj][0] + bx, acc[mi][nj][1] + by);
            float2 v1 = make_float2(acc[mi][nj][2] + bx, acc[mi][nj][3] + by);
            *reinterpret_cast<float2*>(out + (size_t)r0 * NTOT + n0 + cl) = v0;
            *reinterpret_cast<float2*>(out + (size_t)(r0 + 8) * NTOT + n0 + cl) = v1;
        }
    }
}

#define SMEM_BYTES ((4 * TILE_FLOATS + BN) * 4)

extern "C" void kernel_launch(void* const* d_in, const int* in_sizes, int n_in,
                              void* d_out, int out_size) {
    const float* X    = (const float*)d_in[0];
    const float* Wt   = (const float*)d_in[1];
    const float* bias = (const float*)d_in[2];
    float* out = (float*)d_out;

    const int Mrows = in_sizes[0] / KTOT;   // 32768

    // Prepass: round+permute X (64MB) and W (1MB) in one launch.
    prep_kernel<<<2048, 256>>>(X, Wt);

    cudaFuncSetAttribute(linear_tf32_kernel,
                         cudaFuncAttributeMaxDynamicSharedMemorySize, SMEM_BYTES);

    dim3 grid(NTOT / BN, Mrows / BM);  // (4, 256)
    linear_tf32_kernel<<<grid, THREADS, SMEM_BYTES>>>(bias, out);
}

// round 13
// speedup vs baseline: 1.2210x; 1.2210x over previous
#include <cuda_runtime.h>
#include <cstdint>

// ============================================================================
// TF32 mma.sync GEMM: out[32768,512] = X @ W^T + bias.
// R8 base (Wperm: tf32-pre-rounded + column-permuted W; zero-cvt vector B
// fragments; scalar+cvt A path) + NEW: 3-stage cp.async pipeline (prefetch
// distance 2, wait_group(1)), same 16 barriers. To keep 2 CTAs/SM, B smem uses
// exact 128B rows with XOR-4 granule swizzle (c4 ^= (row&1)<<2) instead of
// padding: conflict-free for both STS and LDS.128 fragment phases.
// BM=BN=128, BK=32, 8 warps (4x2), warp tile 32x64, m16n8k8.
// ============================================================================

#define MTOT 32768
#define KTOT 512
#define NTOT 512
#define BM   128
#define BN   128
#define BK   32
#define NKC  (KTOT / BK)     // 16
#define STAGES 3
#define THREADS 256
#define SSA  36              // A smem floats/row (32 data + 4 pad), scalar LDS
#define BROW 32              // B smem floats/row (exact 128B, swizzled)

#define A_TILE (BM * SSA)    // 4608 floats / stage
#define B_TILE (BN * BROW)   // 4096 floats / stage

__device__ float Wperm[(size_t)NTOT * KTOT];   // 1MB: tf32-rounded, permuted

__device__ __forceinline__ uint32_t smem_u32(const void* p) {
    return (uint32_t)__cvta_generic_to_shared(p);
}

__device__ __forceinline__ uint32_t tf32rn(float x) {
    uint32_t y;
    asm("cvt.rna.tf32.f32 %0, %1;" : "=r"(y) : "f"(x));
    return y;
}

#define CP_ASYNC_CG(dst_u32, src_ptr)                                         \
    asm volatile("cp.async.cg.shared.global [%0], [%1], 16;"                  \
                 :: "r"(dst_u32), "l"(src_ptr))
#define CP_COMMIT() asm volatile("cp.async.commit_group;" ::: "memory")
#define CP_WAIT(N)  asm volatile("cp.async.wait_group %0;" :: "n"(N) : "memory")

__device__ __forceinline__ void mma_tf32(float* d, const uint32_t* a,
                                         const uint32_t* b) {
    asm volatile(
        "mma.sync.aligned.m16n8k8.row.col.f32.tf32.tf32.f32 "
        "{%0,%1,%2,%3}, {%4,%5,%6,%7}, {%8,%9}, {%0,%1,%2,%3};"
        : "+f"(d[0]), "+f"(d[1]), "+f"(d[2]), "+f"(d[3])
        : "r"(a[0]), "r"(a[1]), "r"(a[2]), "r"(a[3]), "r"(b[0]), "r"(b[1]));
}

// W prepass: Wperm[n][p(k)] = tf32_round(W[n][k]),
// p(k) = (k & ~15) | ((k & 3) << 2) | ((k >> 2) & 3)
__global__ void wprep_kernel(const float* __restrict__ W) {
    const int n = blockIdx.x;
    for (int c = threadIdx.x; c < KTOT; c += blockDim.x) {
        const uint32_t bits = tf32rn(W[n * KTOT + c]);
        const int p = (c & ~15) | ((c & 3) << 2) | ((c >> 2) & 3);
        Wperm[n * KTOT + p] = __uint_as_float(bits);
    }
}

__global__ void __launch_bounds__(THREADS, 2)
linear_tf32_kernel(const float* __restrict__ X, const float* __restrict__ bias,
                   float* __restrict__ out) {
    extern __shared__ float smem[];
    float* As = smem;                                   // [STAGES][A_TILE]
    float* Bs = smem + STAGES * A_TILE;                 // [STAGES][B_TILE]
    float* bias_s = smem + STAGES * (A_TILE + B_TILE);  // [BN]

    const int tid = threadIdx.x;
    const int wid = tid >> 5;
    const int lid = tid & 31;
    const int g = lid >> 2;          // group id (0..7)
    const int t = lid & 3;           // thread-in-group (0..3)
    const int wm = (wid & 3) * 32;   // warp M offset
    const int wn = (wid >> 2) * 64;  // warp N offset

    const int n0 = blockIdx.x * BN;
    const int m0 = blockIdx.y * BM;

    const float* Ag = X + (size_t)m0 * KTOT;
    const float* Bg = Wperm + (size_t)n0 * KTOT;

    if (tid < BN) bias_s[tid] = bias[n0 + tid];

    const uint32_t as_b = smem_u32(As);
    const uint32_t bs_b = smem_u32(Bs);

    // Staging: idx in [0,1024): row = idx>>3, c4 = idx&7 (16B granules).
    const int sr0 = tid >> 3;
    const int sc4 = tid & 7;

    // -------- prologue: stage chunks 0..STAGES-2 --------
    #pragma unroll
    for (int pc = 0; pc < STAGES - 1; pc++) {
        const int kb = pc * BK;
        const uint32_t an = as_b + pc * A_TILE * 4;
        const uint32_t bn = bs_b + pc * B_TILE * 4;
        #pragma unroll
        for (int i = 0; i < 4; i++) {
            const int row = sr0 + i * 32;
            CP_ASYNC_CG(an + (row * SSA + sc4 * 4) * 4,
                        Ag + (size_t)row * KTOT + kb + sc4 * 4);
        }
        #pragma unroll
        for (int i = 0; i < 4; i++) {
            const int row = sr0 + i * 32;
            const int c4s = sc4 ^ ((row & 1) << 2);    // XOR swizzle
            CP_ASYNC_CG(bn + (row * BROW + c4s * 4) * 4,
                        Bg + (size_t)row * KTOT + kb + sc4 * 4);
        }
        CP_COMMIT();
    }

    float acc[2][8][4];
    #pragma unroll
    for (int mi = 0; mi < 2; mi++)
        #pragma unroll
        for (int nj = 0; nj < 8; nj++)
            #pragma unroll
            for (int e = 0; e < 4; e++) acc[mi][nj][e] = 0.0f;

    for (int kc = 0; kc < NKC; kc++) {
        const int s = kc % STAGES;

        CP_WAIT(STAGES - 2);   // chunk kc landed (kc+1 may stay in flight)
        __syncthreads();       // all warps past compute of kc-1 -> its stage free

        // Prefetch chunk kc+2 into stage (kc+2)%3 (= stage of chunk kc-1).
        if (kc + STAGES - 1 < NKC) {
            const int sn = (kc + STAGES - 1) % STAGES;
            const int kb = (kc + STAGES - 1) * BK;
            const uint32_t an = as_b + sn * A_TILE * 4;
            const uint32_t bn = bs_b + sn * B_TILE * 4;
            #pragma unroll
            for (int i = 0; i < 4; i++) {
                const int row = sr0 + i * 32;
                CP_ASYNC_CG(an + (row * SSA + sc4 * 4) * 4,
                            Ag + (size_t)row * KTOT + kb + sc4 * 4);
            }
            #pragma unroll
            for (int i = 0; i < 4; i++) {
                const int row = sr0 + i * 32;
                const int c4s = sc4 ^ ((row & 1) << 2);
                CP_ASYNC_CG(bn + (row * BROW + c4s * 4) * 4,
                            Bg + (size_t)row * KTOT + kb + sc4 * 4);
            }
        }
        CP_COMMIT();   // empty group when prefetch skipped (keeps counts sane)

        const float* At = As + s * A_TILE;
        const float* Bt = Bs + s * B_TILE;

        #pragma unroll
        for (int G = 0; G < 2; G++) {   // two 16-K groups per chunk
            // B fragments: 8 x LDS.128 (swizzled granule), zero cvt.
            uint32_t bf0[8][2], bf1[8][2];
            #pragma unroll
            for (int nj = 0; nj < 8; nj++) {
                const int n = wn + nj * 8 + g;
                const int c4 = (4 * G + t) ^ ((n & 1) << 2);
                const float4 v = *reinterpret_cast<const float4*>(
                    Bt + n * BROW + c4 * 4);
                bf0[nj][0] = __float_as_uint(v.x);
                bf0[nj][1] = __float_as_uint(v.y);
                bf1[nj][0] = __float_as_uint(v.z);
                bf1[nj][1] = __float_as_uint(v.w);
            }
            #pragma unroll
            for (int ks = 0; ks < 2; ks++) {   // K=8 slices within group
                const int k = G * 16 + ks * 8;
                uint32_t af[2][4];
                #pragma unroll
                for (int mi = 0; mi < 2; mi++) {
                    const int r = wm + mi * 16 + g;
                    af[mi][0] = tf32rn(At[r * SSA + k + t]);
                    af[mi][1] = tf32rn(At[(r + 8) * SSA + k + t]);
                    af[mi][2] = tf32rn(At[r * SSA + k + t + 4]);
                    af[mi][3] = tf32rn(At[(r + 8) * SSA + k + t + 4]);
                }
                #pragma unroll
                for (int mi = 0; mi < 2; mi++)
                    #pragma unroll
                    for (int nj = 0; nj < 8; nj++)
                        mma_tf32(acc[mi][nj], af[mi],
                                 ks ? bf1[nj] : bf0[nj]);
            }
        }
    }

    // -------- epilogue: add bias, store float2 --------
    // (K-permutation only reorders the contraction; output layout untouched.)
    #pragma unroll
    for (int mi = 0; mi < 2; mi++) {
        const int r0 = m0 + wm + mi * 16 + g;
        #pragma unroll
        for (int nj = 0; nj < 8; nj++) {
            const int cl = wn + nj * 8 + 2 * t;
            const float bx = bias_s[cl];
            const float by = bias_s[cl + 1];
            float2 v0 = make_float2(acc[mi][nj][0] + bx, acc[mi][nj][1] + by);
            float2 v1 = make_float2(acc[mi][nj][2] + bx, acc[mi][nj][3] + by);
            *reinterpret_cast<float2*>(out + (size_t)r0 * NTOT + n0 + cl) = v0;
            *reinterpret_cast<float2*>(out + (size_t)(r0 + 8) * NTOT + n0 + cl) = v1;
        }
    }
}

#define SMEM_BYTES ((STAGES * (A_TILE + B_TILE) + BN) * 4)

extern "C" void kernel_launch(void* const* d_in, const int* in_sizes, int n_in,
                              void* d_out, int out_size) {
    const float* X    = (const float*)d_in[0];
    const float* Wt   = (const float*)d_in[1];
    const float* bias = (const float*)d_in[2];
    float* out = (float*)d_out;

    const int Mrows = in_sizes[0] / KTOT;   // 32768

    wprep_kernel<<<NTOT, 256>>>(Wt);

    cudaFuncSetAttribute(linear_tf32_kernel,
                         cudaFuncAttributeMaxDynamicSharedMemorySize, SMEM_BYTES);

    dim3 grid(NTOT / BN, Mrows / BM);  // (4, 256)
    linear_tf32_kernel<<<grid, THREADS, SMEM_BYTES>>>(X, bias, out);
}

// round 16
// speedup vs baseline: 1.4024x; 1.1486x over previous
#include <cuda_runtime.h>
#include <cstdint>

// ============================================================================
// TF32 mma.sync GEMM: out[32768,512] = X @ W^T + bias.
// R14 design (mbarrier producer/consumer pipeline, no per-chunk __syncthreads)
// with the deadlock fixed: cp.async.mbarrier.arrive must be the .noinc form
// (default form increments-then-arrives = net zero = phase never completes).
// try_wait now .acquire.cta with suspend hint.
// Base: Wperm (pre-rounded+permuted W), zero-cvt vector B frags, scalar+cvt A,
// 3 stages, XOR-swizzled exact-128B B rows.
// BM=BN=128, BK=32, 8 warps (4x2), warp tile 32x64, m16n8k8.
// ============================================================================

#define MTOT 32768
#define KTOT 512
#define NTOT 512
#define BM   128
#define BN   128
#define BK   32
#define NKC  (KTOT / BK)     // 16
#define STAGES 3
#define THREADS 256
#define SSA  36              // A smem floats/row (32 data + 4 pad), scalar LDS
#define BROW 32              // B smem floats/row (exact 128B, XOR swizzled)

#define A_TILE (BM * SSA)    // 4608 floats / stage
#define B_TILE (BN * BROW)   // 4096 floats / stage

// float offsets in dynamic smem
#define BIAS_OFF  (STAGES * (A_TILE + B_TILE))          // 26112
#define MBAR_OFF  ((BIAS_OFF + BN) * 4)                 // byte offset, 8B-aligned
// mbarriers: full[0..2] at MBAR_OFF + 8*s, empty[0..2] at MBAR_OFF + 24 + 8*s
#define SMEM_BYTES (MBAR_OFF + 48)

__device__ float Wperm[(size_t)NTOT * KTOT];   // 1MB: tf32-rounded, permuted

__device__ __forceinline__ uint32_t smem_u32(const void* p) {
    return (uint32_t)__cvta_generic_to_shared(p);
}

__device__ __forceinline__ uint32_t tf32rn(float x) {
    uint32_t y;
    asm("cvt.rna.tf32.f32 %0, %1;" : "=r"(y) : "f"(x));
    return y;
}

#define CP_ASYNC_CG(dst_u32, src_ptr)                                         \
    asm volatile("cp.async.cg.shared.global [%0], [%1], 16;"                  \
                 :: "r"(dst_u32), "l"(src_ptr))

__device__ __forceinline__ void mbar_init(uint32_t a, uint32_t n) {
    asm volatile("mbarrier.init.shared.b64 [%0], %1;" :: "r"(a), "r"(n) : "memory");
}
__device__ __forceinline__ void mbar_arrive(uint32_t a) {
    asm volatile("mbarrier.arrive.shared.b64 _, [%0];" :: "r"(a) : "memory");
}
// .noinc: the completion-arrive counts against the init count (default form
// increments pending count at issue -> net zero -> deadlock).
__device__ __forceinline__ void cpasync_mbar_arrive_noinc(uint32_t a) {
    asm volatile("cp.async.mbarrier.arrive.noinc.shared.b64 [%0];"
                 :: "r"(a) : "memory");
}
__device__ __forceinline__ void mbar_wait(uint32_t a, uint32_t parity) {
    asm volatile(
        "{\n\t"
        ".reg .pred P;\n"
        "WL_%=:\n\t"
        "mbarrier.try_wait.parity.acquire.cta.shared::cta.b64 P, [%0], %1, 0x989680;\n\t"
        "@P bra WD_%=;\n\t"
        "bra WL_%=;\n"
        "WD_%=:\n\t"
        "}"
        :: "r"(a), "r"(parity) : "memory");
}

__device__ __forceinline__ void mma_tf32(float* d, const uint32_t* a,
                                         const uint32_t* b) {
    asm volatile(
        "mma.sync.aligned.m16n8k8.row.col.f32.tf32.tf32.f32 "
        "{%0,%1,%2,%3}, {%4,%5,%6,%7}, {%8,%9}, {%0,%1,%2,%3};"
        : "+f"(d[0]), "+f"(d[1]), "+f"(d[2]), "+f"(d[3])
        : "r"(a[0]), "r"(a[1]), "r"(a[2]), "r"(a[3]), "r"(b[0]), "r"(b[1]));
}

// W prepass: Wperm[n][p(k)] = tf32_round(W[n][k]),
// p(k) = (k & ~15) | ((k & 3) << 2) | ((k >> 2) & 3)
__global__ void wprep_kernel(const float* __restrict__ W) {
    const int n = blockIdx.x;
    for (int c = threadIdx.x; c < KTOT; c += blockDim.x) {
        const uint32_t bits = tf32rn(W[n * KTOT + c]);
        const int p = (c & ~15) | ((c & 3) << 2) | ((c >> 2) & 3);
        Wperm[n * KTOT + p] = __uint_as_float(bits);
    }
}

__global__ void __launch_bounds__(THREADS, 2)
linear_tf32_kernel(const float* __restrict__ X, const float* __restrict__ bias,
                   float* __restrict__ out) {
    extern __shared__ float smem[];
    float* As = smem;                        // [STAGES][A_TILE]
    float* Bs = smem + STAGES * A_TILE;      // [STAGES][B_TILE]
    float* bias_s = smem + BIAS_OFF;         // [BN]

    const int tid = threadIdx.x;
    const int wid = tid >> 5;
    const int lid = tid & 31;
    const int g = lid >> 2;          // group id (0..7)
    const int t = lid & 3;           // thread-in-group (0..3)
    const int wm = (wid & 3) * 32;   // warp M offset
    const int wn = (wid >> 2) * 64;  // warp N offset

    const int n0 = blockIdx.x * BN;
    const int m0 = blockIdx.y * BM;

    const float* Ag = X + (size_t)m0 * KTOT;
    const float* Bg = Wperm + (size_t)n0 * KTOT;

    const uint32_t smb = smem_u32(smem);
    const uint32_t full_mb  = smb + MBAR_OFF;        // +8*s
    const uint32_t empty_mb = smb + MBAR_OFF + 24;   // +8*s

    if (tid < BN) bias_s[tid] = bias[n0 + tid];
    if (tid == 0) {
        #pragma unroll
        for (int s = 0; s < STAGES; s++) {
            mbar_init(full_mb + 8 * s, THREADS);
            mbar_init(empty_mb + 8 * s, THREADS);
        }
    }
    __syncthreads();   // mbarriers + bias visible; only CTA-wide sync in kernel

    const uint32_t as_b = smem_u32(As);
    const uint32_t bs_b = smem_u32(Bs);

    // Staging: idx in [0,1024): row = idx>>3, c4 = idx&7 (16B granules).
    const int sr0 = tid >> 3;
    const int sc4 = tid & 7;

    // -------- prologue: stage chunks 0 and 1 --------
    #pragma unroll
    for (int pc = 0; pc < 2; pc++) {
        const int kb = pc * BK;
        const uint32_t an = as_b + pc * A_TILE * 4;
        const uint32_t bn = bs_b + pc * B_TILE * 4;
        #pragma unroll
        for (int i = 0; i < 4; i++) {
            const int row = sr0 + i * 32;
            CP_ASYNC_CG(an + (row * SSA + sc4 * 4) * 4,
                        Ag + (size_t)row * KTOT + kb + sc4 * 4);
        }
        #pragma unroll
        for (int i = 0; i < 4; i++) {
            const int row = sr0 + i * 32;
            const int c4s = sc4 ^ ((row & 1) << 2);
            CP_ASYNC_CG(bn + (row * BROW + c4s * 4) * 4,
                        Bg + (size_t)row * KTOT + kb + sc4 * 4);
        }
        cpasync_mbar_arrive_noinc(full_mb + 8 * pc);
    }

    float acc[2][8][4];
    #pragma unroll
    for (int mi = 0; mi < 2; mi++)
        #pragma unroll
        for (int nj = 0; nj < 8; nj++)
            #pragma unroll
            for (int e = 0; e < 4; e++) acc[mi][nj][e] = 0.0f;

    int s = 0;                 // kc % 3
    uint32_t fullmask = 0;     // phase bits per stage (full waits)
    uint32_t emptymask = 0;    // phase bits per stage (empty waits)

    for (int kc = 0; kc < NKC; kc++) {
        // ---- consume: wait chunk kc staged ----
        mbar_wait(full_mb + 8 * s, (fullmask >> s) & 1);
        fullmask ^= 1u << s;

        const float* At = As + s * A_TILE;
        const float* Bt = Bs + s * B_TILE;

        #pragma unroll
        for (int G = 0; G < 2; G++) {   // two 16-K groups per chunk
            // B fragments: 8 x LDS.128 (swizzled granule), zero cvt.
            uint32_t bf0[8][2], bf1[8][2];
            #pragma unroll
            for (int nj = 0; nj < 8; nj++) {
                const int n = wn + nj * 8 + g;
                const int c4 = (4 * G + t) ^ ((n & 1) << 2);
                const float4 v = *reinterpret_cast<const float4*>(
                    Bt + n * BROW + c4 * 4);
                bf0[nj][0] = __float_as_uint(v.x);
                bf0[nj][1] = __float_as_uint(v.y);
                bf1[nj][0] = __float_as_uint(v.z);
                bf1[nj][1] = __float_as_uint(v.w);
            }
            #pragma unroll
            for (int ks = 0; ks < 2; ks++) {   // K=8 slices within group
                const int k = G * 16 + ks * 8;
                uint32_t af[2][4];
                #pragma unroll
                for (int mi = 0; mi < 2; mi++) {
                    const int r = wm + mi * 16 + g;
                    af[mi][0] = tf32rn(At[r * SSA + k + t]);
                    af[mi][1] = tf32rn(At[(r + 8) * SSA + k + t]);
                    af[mi][2] = tf32rn(At[r * SSA + k + t + 4]);
                    af[mi][3] = tf32rn(At[(r + 8) * SSA + k + t + 4]);
                }
                #pragma unroll
                for (int mi = 0; mi < 2; mi++)
                    #pragma unroll
                    for (int nj = 0; nj < 8; nj++)
                        mma_tf32(acc[mi][nj], af[mi],
                                 ks ? bf1[nj] : bf0[nj]);
            }
        }

        // ---- release stage s (arrive has release semantics) ----
        mbar_arrive(empty_mb + 8 * s);

        // ---- produce: stage chunk kc+2 ----
        const int c = kc + 2;
        if (c < NKC) {
            int sn = s + 2; if (sn >= STAGES) sn -= STAGES;
            if (c >= STAGES) {   // stage reuse: wait until all consumed c-3
                mbar_wait(empty_mb + 8 * sn, (emptymask >> sn) & 1);
                emptymask ^= 1u << sn;
            }
            const int kb = c * BK;
            const uint32_t an = as_b + sn * A_TILE * 4;
            const uint32_t bn = bs_b + sn * B_TILE * 4;
            #pragma unroll
            for (int i = 0; i < 4; i++) {
                const int row = sr0 + i * 32;
                CP_ASYNC_CG(an + (row * SSA + sc4 * 4) * 4,
                            Ag + (size_t)row * KTOT + kb + sc4 * 4);
            }
            #pragma unroll
            for (int i = 0; i < 4; i++) {
                const int row = sr0 + i * 32;
                const int c4s = sc4 ^ ((row & 1) << 2);
                CP_ASYNC_CG(bn + (row * BROW + c4s * 4) * 4,
                            Bg + (size_t)row * KTOT + kb + sc4 * 4);
            }
            cpasync_mbar_arrive_noinc(full_mb + 8 * sn);
        }

        if (++s == STAGES) s = 0;
    }

    // -------- epilogue: add bias, store float2 (per-warp, no sync needed) ----
    #pragma unroll
    for (int mi = 0; mi < 2; mi++) {
        const int r0 = m0 + wm + mi * 16 + g;
        #pragma unroll
        for (int nj = 0; nj < 8; nj++) {
            const int cl = wn + nj * 8 + 2 * t;
            const float bx = bias_s[cl];
            const float by = bias_s[cl + 1];
            float2 v0 = make_float2(acc[mi][nj][0] + bx, acc[mi][nj][1] + by);
            float2 v1 = make_float2(acc[mi][nj][2] + bx, acc[mi][nj][3] + by);
            *reinterpret_cast<float2*>(out + (size_t)r0 * NTOT + n0 + cl) = v0;
            *reinterpret_cast<float2*>(out + (size_t)(r0 + 8) * NTOT + n0 + cl) = v1;
        }
    }
}

extern "C" void kernel_launch(void* const* d_in, const int* in_sizes, int n_in,
                              void* d_out, int out_size) {
    const float* X    = (const float*)d_in[0];
    const float* Wt   = (const float*)d_in[1];
    const float* bias = (const float*)d_in[2];
    float* out = (float*)d_out;

    const int Mrows = in_sizes[0] / KTOT;   // 32768

    wprep_kernel<<<NTOT, 256>>>(Wt);

    cudaFuncSetAttribute(linear_tf32_kernel,
                         cudaFuncAttributeMaxDynamicSharedMemorySize, SMEM_BYTES);

    dim3 grid(NTOT / BN, Mrows / BM);  // (4, 256)
    linear_tf32_kernel<<<grid, THREADS, SMEM_BYTES>>>(X, bias, out);
}